// round 13
// baseline (speedup 1.0000x reference)
#include <cuda_runtime.h>
#include <cstdint>

// ---------------------------------------------------------------------------
// out[b,c] = sum_e y[b,e]*( sum_{w<=v<=i} S3[c,e,(w,v,i)] x_w x_v x_i
//                         + sum_{w<=v}    S2[c,e,(w,v)]   x_w x_v
//                         + sum_w         V1[c,e,w]       x_w )
// Round 13: e-block accumulators (y folded 10x/thread instead of per (pair,e)),
// 2 b's/thread (xp 32 regs) -> ~90 regs, scheduler headroom. Templated
// schedule + LDS.128 streams retained.
// ---------------------------------------------------------------------------

namespace {
constexpr int LDIM = 16;
constexpr int EDIM = 10;
constexpr int CDIM = 256;
constexpr int BDIM = 1024;
constexpr int K3C  = 23;
constexpr int K2C  = 4;

constexpr int NPAIR    = 136;           // (w<=v) pairs, 8 buckets x 17
constexpr int NBUCK    = 8;
constexpr int PPB      = 17;
constexpr int BSTRIDE  = 72;            // ull slots per bucket (even-padded)
constexpr int NSLOT_U  = NBUCK * BSTRIDE;   // 576 ull per e
constexpr int NSLOT_U2 = NSLOT_U / 2;       // 288 ull2 per e
constexpr int NSLOT_F  = 2 * NSLOT_U;       // 1152 floats per e

constexpr int S3_PER_C  = EDIM * NSLOT_F;   // 11520 floats
constexpr int S2U_PER_C = EDIM * NPAIR;     // 1360 ull
constexpr int V1_PER_C  = EDIM * LDIM;      // 160

constexpr int SMEM_MAIN =
    S3_PER_C * 4 +        // 46080
    S2U_PER_C * 8 +       // 10880
    256 * 17 * 4 +        // 17408 x scalars, stride 17
    EDIM * 256 * 4 +      // 10240 scalar y [e][b]
    4 * 256 * 4;          //  4096 reduction (4 psplits)
// = 88704

constexpr int SMEM_KS3 = (K3C * NSLOT_F + EDIM * K3C + 8) * 4;  // ~107 KB

// ---- compile-time pair schedule (device-usable constexpr) -------------------
__host__ __device__ constexpr int class_start(int g) {
    int s = 0;
    for (int g2 = 0; g2 < g; g2++) s += 4 * g2 + 3;
    return s;
}
__host__ __device__ constexpr int rank_g(int r) {
    int g = 0;
    while (g < 7 && class_start(g + 1) <= r) g++;
    return g;
}
__host__ __device__ constexpr int rank_len(int r) { return 8 - rank_g(r); }
__host__ __device__ constexpr int pr_w(int r) {
    const int g = rank_g(r), idx = r - class_start(g);
    return idx < 4 * g + 2 ? (idx >> 1) : (2 * g + 1);
}
__host__ __device__ constexpr int pr_v(int r) {
    const int g = rank_g(r), idx = r - class_start(g);
    return idx < 4 * g + 2 ? (2 * g + (idx & 1)) : (2 * g + 1);
}
__host__ __device__ constexpr int boff2(int B, int J) {
    int o = 0;
    for (int j = 0; j < J; j++) o += (rank_len(j * 8 + B) + 1) / 2;
    return B * (BSTRIDE / 2) + o;
}
}

// ---- device scratch ----------------------------------------------------------
__device__ int   g_pw[NPAIR], g_pv[NPAIR];
__device__ int   g_s2p[NSLOT_F], g_s2i[NSLOT_F];   // float-slot -> pair, i
__device__ float U3symT[K3C * NSLOT_F];            // [k][slot], zero-padded
__device__ float S3g[CDIM * S3_PER_C];             // ~11.8 MB
__device__ unsigned long long S2gu[CDIM * S2U_PER_C];
__device__ float V1g[CDIM * V1_PER_C];

// ---- packed f32x2 helpers (sm_103a) -------------------------------------------
using ull = unsigned long long;
__device__ __forceinline__ ull pk2(float a, float b) {
    ull r;
    asm("mov.b64 %0, {%1, %2};"
        : "=l"(r) : "r"(__float_as_uint(a)), "r"(__float_as_uint(b)));
    return r;
}
__device__ __forceinline__ ull dup2(float a) {
    ull r;
    asm("mov.b64 %0, {%1, %1};" : "=l"(r) : "r"(__float_as_uint(a)));
    return r;
}
__device__ __forceinline__ ull fma2(ull a, ull b, ull c) {
    ull d;
    asm("fma.rn.f32x2 %0, %1, %2, %3;" : "=l"(d) : "l"(a), "l"(b), "l"(c));
    return d;
}
__device__ __forceinline__ void upk2(ull v, float& a, float& b) {
    unsigned int lo, hi;
    asm("mov.b64 {%0, %1}, %2;" : "=r"(lo), "=r"(hi) : "l"(v));
    a = __uint_as_float(lo);
    b = __uint_as_float(hi);
}

// ---- k_tab: runtime twin of the constexpr schedule ---------------------------
__global__ void k_tab() {
    const int tid = threadIdx.x;
    for (int s = tid; s < NSLOT_F; s += 256) { g_s2i[s] = -1; g_s2p[s] = 0; }
    __syncthreads();
    if (tid >= NPAIR) return;

    const int B = tid & 7;
    const int J = tid >> 3;
    const int rank = J * 8 + B;
    const int w = pr_w(rank);
    const int v = pr_v(rank);
    const int L = rank_len(rank);
    const int off_abs = boff2(B, J) * 2;   // ull units
    const int pi = B * PPB + J;

    g_pw[pi] = w;
    g_pv[pi] = v;

    for (int u = 0; u < L; u++)
        for (int r = 0; r < 2; r++) {
            const int s = 2 * (off_abs + u) + r;
            const int i = 14 - 2 * u + r;
            g_s2p[s] = pi;
            g_s2i[s] = (i >= v) ? i : -1;
        }
}

// ---- k_sym: symmetrized U3, transposed [k][slot] ------------------------------
__device__ __forceinline__ float u3at(const float* U3, int a, int b, int c, int k) {
    return U3[((a * 16 + b) * 16 + c) * K3C + k];
}
__global__ void k_sym(const float* __restrict__ U3) {
    const int idx = blockIdx.x * 256 + threadIdx.x;   // 23 * 1152
    if (idx >= K3C * NSLOT_F) return;
    const int s = idx % NSLOT_F;
    const int k = idx / NSLOT_F;
    const int i = g_s2i[s];
    float val = 0.f;
    if (i >= 0) {
        const int pi = g_s2p[s];
        const int w = g_pw[pi], v = g_pv[pi];
        if (w == v && v == i) {
            val = u3at(U3, w, w, w, k);
        } else if (w == v) {
            val = u3at(U3, w, w, i, k) + u3at(U3, w, i, w, k) + u3at(U3, i, w, w, k);
        } else if (v == i) {
            val = u3at(U3, w, v, v, k) + u3at(U3, v, w, v, k) + u3at(U3, v, v, w, k);
        } else {
            val = u3at(U3, w, v, i, k) + u3at(U3, w, i, v, k) +
                  u3at(U3, v, w, i, k) + u3at(U3, v, i, w, k) +
                  u3at(U3, i, w, v, k) + u3at(U3, i, v, w, k);
        }
    }
    U3symT[k * NSLOT_F + s] = val;
}

// ---- k_s3: per-c contraction + fused S2/V1 ------------------------------------
__global__ __launch_bounds__(512, 1)
void k_s3(const float* __restrict__ W3, const float* __restrict__ U2,
          const float* __restrict__ W2, const float* __restrict__ U1,
          const float* __restrict__ W1) {
    extern __shared__ float sm[];
    float* sU = sm;                       // [23][1152]
    float* sW = sm + K3C * NSLOT_F;       // [10][23]
    const int tid = threadIdx.x;
    const int c   = blockIdx.x;

    for (int t = tid; t < K3C * NSLOT_F; t += 512) sU[t] = U3symT[t];
    if (tid < EDIM * K3C) {
        const int e = tid / K3C, k = tid - e * K3C;
        sW[tid] = W3[(e * K3C + k) * CDIM + c];
    }
    __syncthreads();

#pragma unroll 1
    for (int idx = tid; idx < S3_PER_C; idx += 512) {
        const int e = idx / NSLOT_F;
        const int s = idx - e * NSLOT_F;
        float a = 0.f;
#pragma unroll
        for (int k = 0; k < K3C; k++)
            a = fmaf(sU[k * NSLOT_F + s], sW[e * K3C + k], a);
        S3g[c * S3_PER_C + idx] = a;
    }

    for (int t = tid; t < S2U_PER_C; t += 512) {
        const int e = t / NPAIR, pp = t - e * NPAIR;
        const int w = g_pw[pp], v = g_pv[pp];
        float s = 0.f;
#pragma unroll
        for (int k = 0; k < K2C; k++) {
            float u = U2[(w * 16 + v) * K2C + k];
            if (w != v) u += U2[(v * 16 + w) * K2C + k];
            s = fmaf(u, W2[(e * K2C + k) * CDIM + c], s);
        }
        S2gu[c * S2U_PER_C + t] = (ull)__float_as_uint(s);  // (s, 0)
    }
    if (tid < V1_PER_C) {
        const int e = tid >> 4, w = tid & 15;
        V1g[c * V1_PER_C + tid] = U1[w] * W1[e * CDIM + c];
    }
}

// ---- sc_main pair chain: e-block accumulators, 2 b's/thread --------------------
// ya0/ya1[ee] accumulate sum_p P_p * d_{p,e} for the 5 e's of the current block.
template <int B, int J>
struct PairChain {
    static __device__ __forceinline__ void run(
        ull (&ya0)[5], ull (&ya1)[5],
        const ulonglong2* __restrict__ sS3eb,   // pre-offset by eblk*5*NSLOT_U2
        const ull* __restrict__ sS2eb,          // pre-offset by eblk*5*NPAIR
        const float* __restrict__ sXs, int b0, int b1,
        const ull (&xp0)[8], const ull (&xp1)[8])
    {
        constexpr int rank = J * 8 + B;
        constexpr int w    = pr_w(rank);
        constexpr int v    = pr_v(rank);
        constexpr int M    = (rank_len(rank) + 1) / 2;
        constexpr int off2 = boff2(B, J);
        constexpr int p    = B * PPB + J;

        const ull Pd0 = dup2(sXs[b0 * 17 + w] * sXs[b0 * 17 + v]);
        const ull Pd1 = dup2(sXs[b1 * 17 + w] * sXs[b1 * 17 + v]);

#pragma unroll
        for (int ee = 0; ee < 5; ee++) {
            const ulonglong2* st = sS3eb + ee * NSLOT_U2 + off2;
            const ull s2 = sS2eb[ee * NPAIR + p];
            ull d0 = s2, d1 = s2;
#pragma unroll
            for (int m = 0; m < M; m++) {
                const ulonglong2 t = st[m];        // LDS.128 broadcast
                d0 = fma2(t.x, xp0[7 - 2 * m], d0);
                d1 = fma2(t.x, xp1[7 - 2 * m], d1);
                d0 = fma2(t.y, xp0[6 - 2 * m], d0);
                d1 = fma2(t.y, xp1[6 - 2 * m], d1);
            }
            ya0[ee] = fma2(Pd0, d0, ya0[ee]);
            ya1[ee] = fma2(Pd1, d1, ya1[ee]);
        }

        PairChain<B, J + 1>::run(ya0, ya1, sS3eb, sS2eb, sXs, b0, b1, xp0, xp1);
    }
};
template <int B>
struct PairChain<B, PPB> {
    static __device__ __forceinline__ void run(
        ull (&)[5], ull (&)[5],
        const ulonglong2*, const ull*, const float*, int, int,
        const ull (&)[8], const ull (&)[8]) {}
};

// Grid (c=256, btile=4). 512 threads: bg = tid&127 owns b's {bg, bg+128};
// psplit = tid>>7 owns buckets {2*psplit, 2*psplit+1}.
__global__ __launch_bounds__(512, 1)
void sc_main(const float* __restrict__ x, const float* __restrict__ y,
             float* __restrict__ out) {
    extern __shared__ char smraw[];
    float* sS3 = reinterpret_cast<float*>(smraw);
    ull*   sS2 = reinterpret_cast<ull*>(sS3 + S3_PER_C);
    float* sXs = reinterpret_cast<float*>(sS2 + S2U_PER_C);
    float* sYs = sXs + 256 * 17;
    float* red = sYs + EDIM * 256;
    const ulonglong2* sS3u2 = reinterpret_cast<const ulonglong2*>(sS3);

    const int tid    = threadIdx.x;
    const int c      = blockIdx.x;
    const int base   = blockIdx.y * 256;
    const int bg     = tid & 127;
    const int psplit = tid >> 7;

    // ---- stage S3 / S2 (coalesced) ----
    {
        const float4* src = reinterpret_cast<const float4*>(S3g + c * S3_PER_C);
        float4* dst = reinterpret_cast<float4*>(sS3);
        for (int t = tid; t < S3_PER_C / 4; t += 512) dst[t] = src[t];
        for (int t = tid; t < S2U_PER_C; t += 512)
            sS2[t] = S2gu[c * S2U_PER_C + t];
    }
    // ---- stage x scalars ----
#pragma unroll
    for (int t = 0; t < 8; t++) {
        const int idx = tid + t * 512;            // 4096 = 256*16
        const int b = idx >> 4, i = idx & 15;
        sXs[b * 17 + i] = x[((base + b) * CDIM + c) * LDIM + i];
    }
    // ---- stage scalar y [e][b] ----
#pragma unroll
    for (int t = 0; t < 5; t++) {
        const int idx = tid + t * 512;            // 2560 = 10*256
        const int b = idx & 255, e = idx >> 8;
        sYs[e * 256 + b] = y[(base + b) * EDIM + e];
    }
    __syncthreads();

    // ---- per-thread packed x (2 b's) ----
    const int b0 = bg, b1 = bg + 128;
    ull xp0[8], xp1[8];
#pragma unroll
    for (int q = 0; q < 8; q++) {
        xp0[q] = pk2(sXs[b0 * 17 + 2 * q], sXs[b0 * 17 + 2 * q + 1]);
        xp1[q] = pk2(sXs[b1 * 17 + 2 * q], sXs[b1 * 17 + 2 * q + 1]);
    }

    ull acc0 = 0ull, acc1 = 0ull;

#pragma unroll 1
    for (int eblk = 0; eblk < 2; eblk++) {
        ull ya0[5] = {0ull, 0ull, 0ull, 0ull, 0ull};
        ull ya1[5] = {0ull, 0ull, 0ull, 0ull, 0ull};
        const ulonglong2* sS3eb = sS3u2 + eblk * 5 * NSLOT_U2;
        const ull* sS2eb = sS2 + eblk * 5 * NPAIR;

        switch (psplit) {
            case 0:
                PairChain<0, 0>::run(ya0, ya1, sS3eb, sS2eb, sXs, b0, b1, xp0, xp1);
                PairChain<1, 0>::run(ya0, ya1, sS3eb, sS2eb, sXs, b0, b1, xp0, xp1);
                break;
            case 1:
                PairChain<2, 0>::run(ya0, ya1, sS3eb, sS2eb, sXs, b0, b1, xp0, xp1);
                PairChain<3, 0>::run(ya0, ya1, sS3eb, sS2eb, sXs, b0, b1, xp0, xp1);
                break;
            case 2:
                PairChain<4, 0>::run(ya0, ya1, sS3eb, sS2eb, sXs, b0, b1, xp0, xp1);
                PairChain<5, 0>::run(ya0, ya1, sS3eb, sS2eb, sXs, b0, b1, xp0, xp1);
                break;
            default:
                PairChain<6, 0>::run(ya0, ya1, sS3eb, sS2eb, sXs, b0, b1, xp0, xp1);
                PairChain<7, 0>::run(ya0, ya1, sS3eb, sS2eb, sXs, b0, b1, xp0, xp1);
                break;
        }

        // fold element weights: only 10 scalar y loads per thread total
#pragma unroll
        for (int ee = 0; ee < 5; ee++) {
            const int e = eblk * 5 + ee;
            acc0 = fma2(dup2(sYs[e * 256 + b0]), ya0[ee], acc0);
            acc1 = fma2(dup2(sYs[e * 256 + b1]), ya1[ee], acc1);
        }
    }

    float lo, hi;
    float s0, s1;
    upk2(acc0, lo, hi); s0 = lo + hi;
    upk2(acc1, lo, hi); s1 = lo + hi;

    // ---- nu=1 (psplit 0 only) ----
    if (psplit == 0) {
        const float* v1 = V1g + c * V1_PER_C;
        float add0 = 0.f, add1 = 0.f;
#pragma unroll 1
        for (int e = 0; e < EDIM; e++) {
            float t0 = 0.f, t1 = 0.f;
#pragma unroll
            for (int w = 0; w < 16; w++) {
                const float vv = v1[e * 16 + w];
                t0 = fmaf(vv, sXs[b0 * 17 + w], t0);
                t1 = fmaf(vv, sXs[b1 * 17 + w], t1);
            }
            add0 = fmaf(sYs[e * 256 + b0], t0, add0);
            add1 = fmaf(sYs[e * 256 + b1], t1, add1);
        }
        s0 += add0; s1 += add1;
    }

    // ---- deterministic cross-split reduction ----
    red[psplit * 256 + b0] = s0;
    red[psplit * 256 + b1] = s1;
    __syncthreads();
    if (tid < 256) {
        const float s = red[tid] + red[256 + tid] + red[512 + tid] + red[768 + tid];
        out[(base + tid) * CDIM + c] = s;
    }
}

// ---- launch --------------------------------------------------------------------
extern "C" void kernel_launch(void* const* d_in, const int* in_sizes, int n_in,
                              void* d_out, int out_size) {
    const float* x  = (const float*)d_in[0];
    const float* y  = (const float*)d_in[1];
    const float* U3 = (const float*)d_in[2];
    const float* U2 = (const float*)d_in[3];
    const float* U1 = (const float*)d_in[4];
    const float* W3 = (const float*)d_in[5];
    const float* W2 = (const float*)d_in[6];
    const float* W1 = (const float*)d_in[7];
    float* out = (float*)d_out;

    cudaFuncSetAttribute(k_s3, cudaFuncAttributeMaxDynamicSharedMemorySize, SMEM_KS3);
    cudaFuncSetAttribute(sc_main, cudaFuncAttributeMaxDynamicSharedMemorySize, SMEM_MAIN);

    k_tab<<<1, 256>>>();
    k_sym<<<(K3C * NSLOT_F + 255) / 256, 256>>>(U3);
    k_s3<<<CDIM, 512, SMEM_KS3>>>(W3, U2, W2, U1, W1);

    dim3 grid(CDIM, BDIM / 256);
    sc_main<<<grid, 512, SMEM_MAIN>>>(x, y, out);
}

// round 14
// speedup vs baseline: 1.0873x; 1.0873x over previous
#include <cuda_runtime.h>
#include <cstdint>

// ---------------------------------------------------------------------------
// out[b,c] = sum_e y[b,e]*( sum_{w<=v<=i} S3[c,e,(w,v,i)] x_w x_v x_i
//                         + sum_{w<=v}    S2[c,e,(w,v)]   x_w x_v
//                         + sum_w         V1[c,e,w]       x_w )
// Round 14: sc_main = round-12 best (189us). k_s3 processes 2 c's per CTA
// (halves U3symT staging traffic). Everything else unchanged.
// ---------------------------------------------------------------------------

namespace {
constexpr int LDIM = 16;
constexpr int EDIM = 10;
constexpr int CDIM = 256;
constexpr int BDIM = 1024;
constexpr int K3C  = 23;
constexpr int K2C  = 4;

constexpr int NPAIR    = 136;           // (w<=v) pairs, 8 buckets x 17
constexpr int NBUCK    = 8;
constexpr int PPB      = 17;
constexpr int BSTRIDE  = 72;            // ull slots per bucket (even-padded)
constexpr int NSLOT_U  = NBUCK * BSTRIDE;   // 576 ull per e
constexpr int NSLOT_U2 = NSLOT_U / 2;       // 288 ull2 per e
constexpr int NSLOT_F  = 2 * NSLOT_U;       // 1152 floats per e

constexpr int S3_PER_C  = EDIM * NSLOT_F;   // 11520 floats
constexpr int S2U_PER_C = EDIM * NPAIR;     // 1360 ull
constexpr int V1_PER_C  = EDIM * LDIM;      // 160

constexpr int SMEM_MAIN =
    S3_PER_C * 4 +        // 46080
    S2U_PER_C * 8 +       // 10880
    256 * 17 * 4 +        // 17408 x scalars, stride 17
    EDIM * 256 * 4 +      // 10240 y float4 [e][bg][4]
    8 * 256 * 4;          //  8192 reduction
// = 92800

constexpr int SMEM_KS3 = (K3C * NSLOT_F + 2 * EDIM * K3C + 8) * 4;  // ~108 KB

// ---- compile-time pair schedule (device-usable constexpr) -------------------
__host__ __device__ constexpr int class_start(int g) {
    int s = 0;
    for (int g2 = 0; g2 < g; g2++) s += 4 * g2 + 3;
    return s;
}
__host__ __device__ constexpr int rank_g(int r) {
    int g = 0;
    while (g < 7 && class_start(g + 1) <= r) g++;
    return g;
}
__host__ __device__ constexpr int rank_len(int r) { return 8 - rank_g(r); }
__host__ __device__ constexpr int pr_w(int r) {
    const int g = rank_g(r), idx = r - class_start(g);
    return idx < 4 * g + 2 ? (idx >> 1) : (2 * g + 1);
}
__host__ __device__ constexpr int pr_v(int r) {
    const int g = rank_g(r), idx = r - class_start(g);
    return idx < 4 * g + 2 ? (2 * g + (idx & 1)) : (2 * g + 1);
}
__host__ __device__ constexpr int boff2(int B, int J) {
    int o = 0;
    for (int j = 0; j < J; j++) o += (rank_len(j * 8 + B) + 1) / 2;
    return B * (BSTRIDE / 2) + o;
}
}

// ---- device scratch ----------------------------------------------------------
__device__ int   g_pw[NPAIR], g_pv[NPAIR];
__device__ int   g_s2p[NSLOT_F], g_s2i[NSLOT_F];   // float-slot -> pair, i
__device__ float U3symT[K3C * NSLOT_F];            // [k][slot], zero-padded
__device__ float S3g[CDIM * S3_PER_C];             // ~11.8 MB
__device__ unsigned long long S2gu[CDIM * S2U_PER_C];
__device__ float V1g[CDIM * V1_PER_C];

// ---- packed f32x2 helpers (sm_103a) -------------------------------------------
using ull = unsigned long long;
__device__ __forceinline__ ull pk2(float a, float b) {
    ull r;
    asm("mov.b64 %0, {%1, %2};"
        : "=l"(r) : "r"(__float_as_uint(a)), "r"(__float_as_uint(b)));
    return r;
}
__device__ __forceinline__ ull dup2(float a) {
    ull r;
    asm("mov.b64 %0, {%1, %1};" : "=l"(r) : "r"(__float_as_uint(a)));
    return r;
}
__device__ __forceinline__ ull fma2(ull a, ull b, ull c) {
    ull d;
    asm("fma.rn.f32x2 %0, %1, %2, %3;" : "=l"(d) : "l"(a), "l"(b), "l"(c));
    return d;
}
__device__ __forceinline__ void upk2(ull v, float& a, float& b) {
    unsigned int lo, hi;
    asm("mov.b64 {%0, %1}, %2;" : "=r"(lo), "=r"(hi) : "l"(v));
    a = __uint_as_float(lo);
    b = __uint_as_float(hi);
}

// ---- k_tab: runtime twin of the constexpr schedule ---------------------------
__global__ void k_tab() {
    const int tid = threadIdx.x;
    for (int s = tid; s < NSLOT_F; s += 256) { g_s2i[s] = -1; g_s2p[s] = 0; }
    __syncthreads();
    if (tid >= NPAIR) return;

    const int B = tid & 7;
    const int J = tid >> 3;
    const int rank = J * 8 + B;
    const int w = pr_w(rank);
    const int v = pr_v(rank);
    const int L = rank_len(rank);
    const int off_abs = boff2(B, J) * 2;   // ull units
    const int pi = B * PPB + J;

    g_pw[pi] = w;
    g_pv[pi] = v;

    for (int u = 0; u < L; u++)
        for (int r = 0; r < 2; r++) {
            const int s = 2 * (off_abs + u) + r;
            const int i = 14 - 2 * u + r;
            g_s2p[s] = pi;
            g_s2i[s] = (i >= v) ? i : -1;
        }
}

// ---- k_sym: symmetrized U3, transposed [k][slot] ------------------------------
__device__ __forceinline__ float u3at(const float* U3, int a, int b, int c, int k) {
    return U3[((a * 16 + b) * 16 + c) * K3C + k];
}
__global__ void k_sym(const float* __restrict__ U3) {
    const int idx = blockIdx.x * 256 + threadIdx.x;   // 23 * 1152
    if (idx >= K3C * NSLOT_F) return;
    const int s = idx % NSLOT_F;
    const int k = idx / NSLOT_F;
    const int i = g_s2i[s];
    float val = 0.f;
    if (i >= 0) {
        const int pi = g_s2p[s];
        const int w = g_pw[pi], v = g_pv[pi];
        if (w == v && v == i) {
            val = u3at(U3, w, w, w, k);
        } else if (w == v) {
            val = u3at(U3, w, w, i, k) + u3at(U3, w, i, w, k) + u3at(U3, i, w, w, k);
        } else if (v == i) {
            val = u3at(U3, w, v, v, k) + u3at(U3, v, w, v, k) + u3at(U3, v, v, w, k);
        } else {
            val = u3at(U3, w, v, i, k) + u3at(U3, w, i, v, k) +
                  u3at(U3, v, w, i, k) + u3at(U3, v, i, w, k) +
                  u3at(U3, i, w, v, k) + u3at(U3, i, v, w, k);
        }
    }
    U3symT[k * NSLOT_F + s] = val;
}

// ---- k_s3: per-c contraction + fused S2/V1, TWO c's per CTA -------------------
__global__ __launch_bounds__(512, 1)
void k_s3(const float* __restrict__ W3, const float* __restrict__ U2,
          const float* __restrict__ W2, const float* __restrict__ U1,
          const float* __restrict__ W1) {
    extern __shared__ float sm[];
    float* sU = sm;                       // [23][1152]  (shared across both c's)
    float* sW = sm + K3C * NSLOT_F;       // [2][10][23]
    const int tid   = threadIdx.x;
    const int cpair = blockIdx.x;         // 0..127

    for (int t = tid; t < K3C * NSLOT_F; t += 512) sU[t] = U3symT[t];
    if (tid < 2 * EDIM * K3C) {
        const int cc  = tid / (EDIM * K3C);
        const int rem = tid - cc * (EDIM * K3C);
        const int e = rem / K3C, k = rem - e * K3C;
        sW[tid] = W3[(e * K3C + k) * CDIM + (cpair * 2 + cc)];
    }
    __syncthreads();

#pragma unroll 1
    for (int cc = 0; cc < 2; cc++) {
        const int c = cpair * 2 + cc;
        const float* sWc = sW + cc * EDIM * K3C;

#pragma unroll 1
        for (int idx = tid; idx < S3_PER_C; idx += 512) {
            const int e = idx / NSLOT_F;
            const int s = idx - e * NSLOT_F;
            float a = 0.f;
#pragma unroll
            for (int k = 0; k < K3C; k++)
                a = fmaf(sU[k * NSLOT_F + s], sWc[e * K3C + k], a);
            S3g[c * S3_PER_C + idx] = a;
        }

        for (int t = tid; t < S2U_PER_C; t += 512) {
            const int e = t / NPAIR, pp = t - e * NPAIR;
            const int w = g_pw[pp], v = g_pv[pp];
            float s = 0.f;
#pragma unroll
            for (int k = 0; k < K2C; k++) {
                float u = U2[(w * 16 + v) * K2C + k];
                if (w != v) u += U2[(v * 16 + w) * K2C + k];
                s = fmaf(u, W2[(e * K2C + k) * CDIM + c], s);
            }
            S2gu[c * S2U_PER_C + t] = (ull)__float_as_uint(s);  // (s, 0)
        }
        if (tid < V1_PER_C) {
            const int e = tid >> 4, w = tid & 15;
            V1g[c * V1_PER_C + tid] = U1[w] * W1[e * CDIM + c];
        }
    }
}

// ---- sc_main: dot with float4 y + e-unroll 2 (round-12 best, unchanged) --------
template <int M>
__device__ __forceinline__ void dot_block(
    const ulonglong2* __restrict__ st0, const ull* __restrict__ s2p,
    const float4* __restrict__ sY4, int bg,
    const ull (&xp0)[8], const ull (&xp1)[8], const ull (&xp2)[8], const ull (&xp3)[8],
    ull& ya0, ull& ya1, ull& ya2, ull& ya3)
{
#pragma unroll 2
    for (int e = 0; e < EDIM; e++) {
        const ulonglong2* st = st0 + e * NSLOT_U2;
        const ull s2 = s2p[e * NPAIR];
        const float4 yv = sY4[e * 64 + bg];    // one LDS.128 per (pair,e)
        ull d0 = s2, d1 = s2, d2 = s2, d3 = s2;
#pragma unroll
        for (int m = 0; m < M; m++) {
            const ulonglong2 t = st[m];        // LDS.128 broadcast
            d0 = fma2(t.x, xp0[7 - 2 * m], d0);
            d1 = fma2(t.x, xp1[7 - 2 * m], d1);
            d2 = fma2(t.x, xp2[7 - 2 * m], d2);
            d3 = fma2(t.x, xp3[7 - 2 * m], d3);
            d0 = fma2(t.y, xp0[6 - 2 * m], d0);
            d1 = fma2(t.y, xp1[6 - 2 * m], d1);
            d2 = fma2(t.y, xp2[6 - 2 * m], d2);
            d3 = fma2(t.y, xp3[6 - 2 * m], d3);
        }
        ya0 = fma2(d0, dup2(yv.x), ya0);
        ya1 = fma2(d1, dup2(yv.y), ya1);
        ya2 = fma2(d2, dup2(yv.z), ya2);
        ya3 = fma2(d3, dup2(yv.w), ya3);
    }
}

// Recursive fully-unrolled pair chain for bucket B: all (w,v,M,off,p) constexpr.
template <int B, int J>
struct PairChain {
    static __device__ __forceinline__ void run(
        const ulonglong2* __restrict__ sS3u2, const ull* __restrict__ sS2,
        const float* __restrict__ sXs, const float4* __restrict__ sY4,
        int bg, int b0, int b1, int b2, int b3,
        const ull (&xp0)[8], const ull (&xp1)[8], const ull (&xp2)[8], const ull (&xp3)[8],
        ull& acc0, ull& acc1, ull& acc2, ull& acc3)
    {
        constexpr int rank = J * 8 + B;
        constexpr int w    = pr_w(rank);
        constexpr int v    = pr_v(rank);
        constexpr int M    = (rank_len(rank) + 1) / 2;
        constexpr int off2 = boff2(B, J);
        constexpr int p    = B * PPB + J;

        const float P0 = sXs[b0 * 17 + w] * sXs[b0 * 17 + v];
        const float P1 = sXs[b1 * 17 + w] * sXs[b1 * 17 + v];
        const float P2 = sXs[b2 * 17 + w] * sXs[b2 * 17 + v];
        const float P3 = sXs[b3 * 17 + w] * sXs[b3 * 17 + v];
        ull ya0 = 0ull, ya1 = 0ull, ya2 = 0ull, ya3 = 0ull;
        dot_block<M>(sS3u2 + off2, sS2 + p, sY4, bg, xp0, xp1, xp2, xp3,
                     ya0, ya1, ya2, ya3);
        acc0 = fma2(dup2(P0), ya0, acc0);
        acc1 = fma2(dup2(P1), ya1, acc1);
        acc2 = fma2(dup2(P2), ya2, acc2);
        acc3 = fma2(dup2(P3), ya3, acc3);

        PairChain<B, J + 1>::run(sS3u2, sS2, sXs, sY4, bg, b0, b1, b2, b3,
                                 xp0, xp1, xp2, xp3, acc0, acc1, acc2, acc3);
    }
};
template <int B>
struct PairChain<B, PPB> {
    static __device__ __forceinline__ void run(
        const ulonglong2*, const ull*, const float*, const float4*,
        int, int, int, int, int,
        const ull (&)[8], const ull (&)[8], const ull (&)[8], const ull (&)[8],
        ull&, ull&, ull&, ull&) {}
};

// Grid (c=256, btile=4). 512 threads: bg = tid&63 owns 4 b's; psplit = tid>>6
// owns one bucket (compile-time schedule). Lanes carry (even-i, odd-i).
__global__ __launch_bounds__(512, 1)
void sc_main(const float* __restrict__ x, const float* __restrict__ y,
             float* __restrict__ out) {
    extern __shared__ char smraw[];
    float* sS3 = reinterpret_cast<float*>(smraw);
    ull*   sS2 = reinterpret_cast<ull*>(sS3 + S3_PER_C);
    float* sXs = reinterpret_cast<float*>(sS2 + S2U_PER_C);
    float* sYf = sXs + 256 * 17;                 // float4 [e][bg][4]
    float* red = sYf + EDIM * 256;
    const ulonglong2* sS3u2 = reinterpret_cast<const ulonglong2*>(sS3);
    const float4* sY4 = reinterpret_cast<const float4*>(sYf);

    const int tid    = threadIdx.x;
    const int c      = blockIdx.x;
    const int base   = blockIdx.y * 256;
    const int bg     = tid & 63;
    const int psplit = tid >> 6;

    // ---- stage S3 / S2 (coalesced) ----
    {
        const float4* src = reinterpret_cast<const float4*>(S3g + c * S3_PER_C);
        float4* dst = reinterpret_cast<float4*>(sS3);
        for (int t = tid; t < S3_PER_C / 4; t += 512) dst[t] = src[t];
        for (int t = tid; t < S2U_PER_C; t += 512)
            sS2[t] = S2gu[c * S2U_PER_C + t];
    }
    // ---- stage x scalars ----
#pragma unroll
    for (int t = 0; t < 8; t++) {
        const int idx = tid + t * 512;            // 4096 = 256*16
        const int b = idx >> 4, i = idx & 15;
        sXs[b * 17 + i] = x[((base + b) * CDIM + c) * LDIM + i];
    }
    // ---- stage y float4 [e][bg][quad] ----
#pragma unroll
    for (int t = 0; t < 5; t++) {
        const int idx = tid + t * 512;            // 2560 = 10*256
        const int b = idx & 255, e = idx >> 8;
        sYf[e * 256 + (b & 63) * 4 + (b >> 6)] = y[(base + b) * EDIM + e];
    }
    __syncthreads();

    // ---- per-thread packed x (4 b's) ----
    const int b0 = bg, b1 = bg + 64, b2 = bg + 128, b3 = bg + 192;
    ull xp0[8], xp1[8], xp2[8], xp3[8];
#pragma unroll
    for (int q = 0; q < 8; q++) {
        xp0[q] = pk2(sXs[b0 * 17 + 2 * q], sXs[b0 * 17 + 2 * q + 1]);
        xp1[q] = pk2(sXs[b1 * 17 + 2 * q], sXs[b1 * 17 + 2 * q + 1]);
        xp2[q] = pk2(sXs[b2 * 17 + 2 * q], sXs[b2 * 17 + 2 * q + 1]);
        xp3[q] = pk2(sXs[b3 * 17 + 2 * q], sXs[b3 * 17 + 2 * q + 1]);
    }

    ull acc0 = 0ull, acc1 = 0ull, acc2 = 0ull, acc3 = 0ull;

    // one warp-uniform dispatch; each bucket fully unrolled at compile time
    switch (psplit) {
        case 0: PairChain<0, 0>::run(sS3u2, sS2, sXs, sY4, bg, b0, b1, b2, b3, xp0, xp1, xp2, xp3, acc0, acc1, acc2, acc3); break;
        case 1: PairChain<1, 0>::run(sS3u2, sS2, sXs, sY4, bg, b0, b1, b2, b3, xp0, xp1, xp2, xp3, acc0, acc1, acc2, acc3); break;
        case 2: PairChain<2, 0>::run(sS3u2, sS2, sXs, sY4, bg, b0, b1, b2, b3, xp0, xp1, xp2, xp3, acc0, acc1, acc2, acc3); break;
        case 3: PairChain<3, 0>::run(sS3u2, sS2, sXs, sY4, bg, b0, b1, b2, b3, xp0, xp1, xp2, xp3, acc0, acc1, acc2, acc3); break;
        case 4: PairChain<4, 0>::run(sS3u2, sS2, sXs, sY4, bg, b0, b1, b2, b3, xp0, xp1, xp2, xp3, acc0, acc1, acc2, acc3); break;
        case 5: PairChain<5, 0>::run(sS3u2, sS2, sXs, sY4, bg, b0, b1, b2, b3, xp0, xp1, xp2, xp3, acc0, acc1, acc2, acc3); break;
        case 6: PairChain<6, 0>::run(sS3u2, sS2, sXs, sY4, bg, b0, b1, b2, b3, xp0, xp1, xp2, xp3, acc0, acc1, acc2, acc3); break;
        default: PairChain<7, 0>::run(sS3u2, sS2, sXs, sY4, bg, b0, b1, b2, b3, xp0, xp1, xp2, xp3, acc0, acc1, acc2, acc3); break;
    }

    float lo, hi;
    float s0, s1, s2v, s3v;
    upk2(acc0, lo, hi); s0  = lo + hi;
    upk2(acc1, lo, hi); s1  = lo + hi;
    upk2(acc2, lo, hi); s2v = lo + hi;
    upk2(acc3, lo, hi); s3v = lo + hi;

    // ---- nu=1 (psplit 0 only) ----
    if (psplit == 0) {
        const float* v1 = V1g + c * V1_PER_C;
        float add0 = 0.f, add1 = 0.f, add2 = 0.f, add3 = 0.f;
#pragma unroll 1
        for (int e = 0; e < EDIM; e++) {
            float t0 = 0.f, t1 = 0.f, t2 = 0.f, t3 = 0.f;
#pragma unroll
            for (int w = 0; w < 16; w++) {
                const float vv = v1[e * 16 + w];
                t0 = fmaf(vv, sXs[b0 * 17 + w], t0);
                t1 = fmaf(vv, sXs[b1 * 17 + w], t1);
                t2 = fmaf(vv, sXs[b2 * 17 + w], t2);
                t3 = fmaf(vv, sXs[b3 * 17 + w], t3);
            }
            const float4 yv = sY4[e * 64 + bg];
            add0 = fmaf(yv.x, t0, add0);
            add1 = fmaf(yv.y, t1, add1);
            add2 = fmaf(yv.z, t2, add2);
            add3 = fmaf(yv.w, t3, add3);
        }
        s0 += add0; s1 += add1; s2v += add2; s3v += add3;
    }

    // ---- deterministic cross-split reduction ----
    red[psplit * 256 + b0] = s0;
    red[psplit * 256 + b1] = s1;
    red[psplit * 256 + b2] = s2v;
    red[psplit * 256 + b3] = s3v;
    __syncthreads();
    if (tid < 256) {
        float s = 0.f;
#pragma unroll
        for (int k = 0; k < 8; k++) s += red[k * 256 + tid];
        out[(base + tid) * CDIM + c] = s;
    }
}

// ---- launch --------------------------------------------------------------------
extern "C" void kernel_launch(void* const* d_in, const int* in_sizes, int n_in,
                              void* d_out, int out_size) {
    const float* x  = (const float*)d_in[0];
    const float* y  = (const float*)d_in[1];
    const float* U3 = (const float*)d_in[2];
    const float* U2 = (const float*)d_in[3];
    const float* U1 = (const float*)d_in[4];
    const float* W3 = (const float*)d_in[5];
    const float* W2 = (const float*)d_in[6];
    const float* W1 = (const float*)d_in[7];
    float* out = (float*)d_out;

    cudaFuncSetAttribute(k_s3, cudaFuncAttributeMaxDynamicSharedMemorySize, SMEM_KS3);
    cudaFuncSetAttribute(sc_main, cudaFuncAttributeMaxDynamicSharedMemorySize, SMEM_MAIN);

    k_tab<<<1, 256>>>();
    k_sym<<<(K3C * NSLOT_F + 255) / 256, 256>>>(U3);
    k_s3<<<CDIM / 2, 512, SMEM_KS3>>>(W3, U2, W2, U1, W1);

    dim3 grid(CDIM, BDIM / 256);
    sc_main<<<grid, 512, SMEM_MAIN>>>(x, y, out);
}

// round 15
// speedup vs baseline: 1.0978x; 1.0096x over previous
#include <cuda_runtime.h>
#include <cstdint>

// ---------------------------------------------------------------------------
// out[b,c] = sum_e y[b,e]*( sum_{w<=v<=i} S3[c,e,(w,v,i)] x_w x_v x_i
//                         + sum_{w<=v}    S2[c,e,(w,v)]   x_w x_v
//                         + sum_w         U1[w] W1[e,c]   x_w )
// Round 15: S3/S2 computed in-CTA (no k_s3, no 11.8MB DRAM round-trip).
// Hot loop identical to round-12 best (188us).
// ---------------------------------------------------------------------------

namespace {
constexpr int LDIM = 16;
constexpr int EDIM = 10;
constexpr int CDIM = 256;
constexpr int BDIM = 1024;
constexpr int K3C  = 23;
constexpr int K2C  = 4;
constexpr int KPAD = 24;                // padded k-stride for U3symS

constexpr int NPAIR    = 136;           // (w<=v) pairs, 8 buckets x 17
constexpr int NBUCK    = 8;
constexpr int PPB      = 17;
constexpr int BSTRIDE  = 72;            // ull slots per bucket (even-padded)
constexpr int NSLOT_U  = NBUCK * BSTRIDE;   // 576 ull per e
constexpr int NSLOT_U2 = NSLOT_U / 2;       // 288 ull2 per e
constexpr int NSLOT_F  = 2 * NSLOT_U;       // 1152 floats per e

constexpr int S3_PER_C  = EDIM * NSLOT_F;   // 11520 floats
constexpr int S2U_PER_C = EDIM * NPAIR;     // 1360 ull

constexpr int SMEM_MAIN =
    S3_PER_C * 4 +        // 46080
    S2U_PER_C * 8 +       // 10880
    256 * 17 * 4 +        // 17408 x scalars, stride 17
    EDIM * 256 * 4 +      // 10240 y float4 [e][bg][4]
    8 * 256 * 4;          //  8192 reduction (reused as sW3 during setup)
// = 92800

// ---- compile-time pair schedule (device-usable constexpr) -------------------
__host__ __device__ constexpr int class_start(int g) {
    int s = 0;
    for (int g2 = 0; g2 < g; g2++) s += 4 * g2 + 3;
    return s;
}
__host__ __device__ constexpr int rank_g(int r) {
    int g = 0;
    while (g < 7 && class_start(g + 1) <= r) g++;
    return g;
}
__host__ __device__ constexpr int rank_len(int r) { return 8 - rank_g(r); }
__host__ __device__ constexpr int pr_w(int r) {
    const int g = rank_g(r), idx = r - class_start(g);
    return idx < 4 * g + 2 ? (idx >> 1) : (2 * g + 1);
}
__host__ __device__ constexpr int pr_v(int r) {
    const int g = rank_g(r), idx = r - class_start(g);
    return idx < 4 * g + 2 ? (2 * g + (idx & 1)) : (2 * g + 1);
}
__host__ __device__ constexpr int boff2(int B, int J) {
    int o = 0;
    for (int j = 0; j < J; j++) o += (rank_len(j * 8 + B) + 1) / 2;
    return B * (BSTRIDE / 2) + o;
}
}

// ---- device scratch ----------------------------------------------------------
__device__ int   g_pw[NPAIR], g_pv[NPAIR];
__device__ int   g_s2p[NSLOT_F], g_s2i[NSLOT_F];   // float-slot -> pair, i
__device__ float U3symS[NSLOT_F * KPAD];           // [slot][24], zero-padded

// ---- packed f32x2 helpers (sm_103a) -------------------------------------------
using ull = unsigned long long;
__device__ __forceinline__ ull pk2(float a, float b) {
    ull r;
    asm("mov.b64 %0, {%1, %2};"
        : "=l"(r) : "r"(__float_as_uint(a)), "r"(__float_as_uint(b)));
    return r;
}
__device__ __forceinline__ ull dup2(float a) {
    ull r;
    asm("mov.b64 %0, {%1, %1};" : "=l"(r) : "r"(__float_as_uint(a)));
    return r;
}
__device__ __forceinline__ ull fma2(ull a, ull b, ull c) {
    ull d;
    asm("fma.rn.f32x2 %0, %1, %2, %3;" : "=l"(d) : "l"(a), "l"(b), "l"(c));
    return d;
}
__device__ __forceinline__ void upk2(ull v, float& a, float& b) {
    unsigned int lo, hi;
    asm("mov.b64 {%0, %1}, %2;" : "=r"(lo), "=r"(hi) : "l"(v));
    a = __uint_as_float(lo);
    b = __uint_as_float(hi);
}

// ---- k_tab: runtime twin of the constexpr schedule ---------------------------
__global__ void k_tab() {
    const int tid = threadIdx.x;
    for (int s = tid; s < NSLOT_F; s += 256) { g_s2i[s] = -1; g_s2p[s] = 0; }
    __syncthreads();
    if (tid >= NPAIR) return;

    const int B = tid & 7;
    const int J = tid >> 3;
    const int rank = J * 8 + B;
    const int w = pr_w(rank);
    const int v = pr_v(rank);
    const int L = rank_len(rank);
    const int off_abs = boff2(B, J) * 2;   // ull units
    const int pi = B * PPB + J;

    g_pw[pi] = w;
    g_pv[pi] = v;

    for (int u = 0; u < L; u++)
        for (int r = 0; r < 2; r++) {
            const int s = 2 * (off_abs + u) + r;
            const int i = 14 - 2 * u + r;
            g_s2p[s] = pi;
            g_s2i[s] = (i >= v) ? i : -1;
        }
}

// ---- k_sym: symmetrized U3, s-major [slot][24] --------------------------------
__device__ __forceinline__ float u3at(const float* U3, int a, int b, int c, int k) {
    return U3[((a * 16 + b) * 16 + c) * K3C + k];
}
__global__ void k_sym(const float* __restrict__ U3) {
    const int idx = blockIdx.x * 256 + threadIdx.x;   // 1152 * 24
    if (idx >= NSLOT_F * KPAD) return;
    const int k = idx % KPAD;
    const int s = idx / KPAD;
    float val = 0.f;
    const int i = g_s2i[s];
    if (k < K3C && i >= 0) {
        const int pi = g_s2p[s];
        const int w = g_pw[pi], v = g_pv[pi];
        if (w == v && v == i) {
            val = u3at(U3, w, w, w, k);
        } else if (w == v) {
            val = u3at(U3, w, w, i, k) + u3at(U3, w, i, w, k) + u3at(U3, i, w, w, k);
        } else if (v == i) {
            val = u3at(U3, w, v, v, k) + u3at(U3, v, w, v, k) + u3at(U3, v, v, w, k);
        } else {
            val = u3at(U3, w, v, i, k) + u3at(U3, w, i, v, k) +
                  u3at(U3, v, w, i, k) + u3at(U3, v, i, w, k) +
                  u3at(U3, i, w, v, k) + u3at(U3, i, v, w, k);
        }
    }
    U3symS[s * KPAD + k] = val;
}

// ---- sc_main: dot with float4 y + e-unroll 2 (round-12 hot loop) ---------------
template <int M>
__device__ __forceinline__ void dot_block(
    const ulonglong2* __restrict__ st0, const ull* __restrict__ s2p,
    const float4* __restrict__ sY4, int bg,
    const ull (&xp0)[8], const ull (&xp1)[8], const ull (&xp2)[8], const ull (&xp3)[8],
    ull& ya0, ull& ya1, ull& ya2, ull& ya3)
{
#pragma unroll 2
    for (int e = 0; e < EDIM; e++) {
        const ulonglong2* st = st0 + e * NSLOT_U2;
        const ull s2 = s2p[e * NPAIR];
        const float4 yv = sY4[e * 64 + bg];    // one LDS.128 per (pair,e)
        ull d0 = s2, d1 = s2, d2 = s2, d3 = s2;
#pragma unroll
        for (int m = 0; m < M; m++) {
            const ulonglong2 t = st[m];        // LDS.128 broadcast
            d0 = fma2(t.x, xp0[7 - 2 * m], d0);
            d1 = fma2(t.x, xp1[7 - 2 * m], d1);
            d2 = fma2(t.x, xp2[7 - 2 * m], d2);
            d3 = fma2(t.x, xp3[7 - 2 * m], d3);
            d0 = fma2(t.y, xp0[6 - 2 * m], d0);
            d1 = fma2(t.y, xp1[6 - 2 * m], d1);
            d2 = fma2(t.y, xp2[6 - 2 * m], d2);
            d3 = fma2(t.y, xp3[6 - 2 * m], d3);
        }
        ya0 = fma2(d0, dup2(yv.x), ya0);
        ya1 = fma2(d1, dup2(yv.y), ya1);
        ya2 = fma2(d2, dup2(yv.z), ya2);
        ya3 = fma2(d3, dup2(yv.w), ya3);
    }
}

// Recursive fully-unrolled pair chain for bucket B: all (w,v,M,off,p) constexpr.
template <int B, int J>
struct PairChain {
    static __device__ __forceinline__ void run(
        const ulonglong2* __restrict__ sS3u2, const ull* __restrict__ sS2,
        const float* __restrict__ sXs, const float4* __restrict__ sY4,
        int bg, int b0, int b1, int b2, int b3,
        const ull (&xp0)[8], const ull (&xp1)[8], const ull (&xp2)[8], const ull (&xp3)[8],
        ull& acc0, ull& acc1, ull& acc2, ull& acc3)
    {
        constexpr int rank = J * 8 + B;
        constexpr int w    = pr_w(rank);
        constexpr int v    = pr_v(rank);
        constexpr int M    = (rank_len(rank) + 1) / 2;
        constexpr int off2 = boff2(B, J);
        constexpr int p    = B * PPB + J;

        const float P0 = sXs[b0 * 17 + w] * sXs[b0 * 17 + v];
        const float P1 = sXs[b1 * 17 + w] * sXs[b1 * 17 + v];
        const float P2 = sXs[b2 * 17 + w] * sXs[b2 * 17 + v];
        const float P3 = sXs[b3 * 17 + w] * sXs[b3 * 17 + v];
        ull ya0 = 0ull, ya1 = 0ull, ya2 = 0ull, ya3 = 0ull;
        dot_block<M>(sS3u2 + off2, sS2 + p, sY4, bg, xp0, xp1, xp2, xp3,
                     ya0, ya1, ya2, ya3);
        acc0 = fma2(dup2(P0), ya0, acc0);
        acc1 = fma2(dup2(P1), ya1, acc1);
        acc2 = fma2(dup2(P2), ya2, acc2);
        acc3 = fma2(dup2(P3), ya3, acc3);

        PairChain<B, J + 1>::run(sS3u2, sS2, sXs, sY4, bg, b0, b1, b2, b3,
                                 xp0, xp1, xp2, xp3, acc0, acc1, acc2, acc3);
    }
};
template <int B>
struct PairChain<B, PPB> {
    static __device__ __forceinline__ void run(
        const ulonglong2*, const ull*, const float*, const float4*,
        int, int, int, int, int,
        const ull (&)[8], const ull (&)[8], const ull (&)[8], const ull (&)[8],
        ull&, ull&, ull&, ull&) {}
};

// Grid (c=256, btile=4). 512 threads: bg = tid&63 owns 4 b's; psplit = tid>>6
// owns one bucket (compile-time schedule). Lanes carry (even-i, odd-i).
__global__ __launch_bounds__(512, 1)
void sc_main(const float* __restrict__ x, const float* __restrict__ y,
             const float* __restrict__ W3, const float* __restrict__ U2,
             const float* __restrict__ W2, const float* __restrict__ U1,
             const float* __restrict__ W1, float* __restrict__ out) {
    extern __shared__ char smraw[];
    float* sS3 = reinterpret_cast<float*>(smraw);
    ull*   sS2 = reinterpret_cast<ull*>(sS3 + S3_PER_C);
    float* sXs = reinterpret_cast<float*>(sS2 + S2U_PER_C);
    float* sYf = sXs + 256 * 17;                 // float4 [e][bg][4]
    float* red = sYf + EDIM * 256;               // doubles as sW3 during setup
    const ulonglong2* sS3u2 = reinterpret_cast<const ulonglong2*>(sS3);
    const float4* sY4 = reinterpret_cast<const float4*>(sYf);
    float* sW3 = red;                            // [10][24], 960B < 8KB

    const int tid    = threadIdx.x;
    const int c      = blockIdx.x;
    const int base   = blockIdx.y * 256;
    const int bg     = tid & 63;
    const int psplit = tid >> 6;

    // ---- stage x scalars ----
#pragma unroll
    for (int t = 0; t < 8; t++) {
        const int idx = tid + t * 512;            // 4096 = 256*16
        const int b = idx >> 4, i = idx & 15;
        sXs[b * 17 + i] = x[((base + b) * CDIM + c) * LDIM + i];
    }
    // ---- stage y float4 [e][bg][quad] ----
#pragma unroll
    for (int t = 0; t < 5; t++) {
        const int idx = tid + t * 512;            // 2560 = 10*256
        const int b = idx & 255, e = idx >> 8;
        sYf[e * 256 + (b & 63) * 4 + (b >> 6)] = y[(base + b) * EDIM + e];
    }
    // ---- stage W3 column [10][24] ----
    if (tid < EDIM * KPAD) {
        const int e = tid / KPAD, k = tid % KPAD;
        sW3[tid] = (k < K3C) ? W3[(e * K3C + k) * CDIM + c] : 0.f;
    }
    __syncthreads();

    // ---- compute sS3 in-CTA: sS3[e*1152+s] = sum_k U3symS[s][k]*sW3[e][k] ----
#pragma unroll 1
    for (int s = tid; s < NSLOT_F; s += 512) {
        float4 u[6];
        const float4* usrc = reinterpret_cast<const float4*>(U3symS + s * KPAD);
#pragma unroll
        for (int q = 0; q < 6; q++) u[q] = usrc[q];
        const float uf[24] = {u[0].x, u[0].y, u[0].z, u[0].w, u[1].x, u[1].y,
                              u[1].z, u[1].w, u[2].x, u[2].y, u[2].z, u[2].w,
                              u[3].x, u[3].y, u[3].z, u[3].w, u[4].x, u[4].y,
                              u[4].z, u[4].w, u[5].x, u[5].y, u[5].z, u[5].w};
#pragma unroll 1
        for (int e = 0; e < EDIM; e++) {
            float a = 0.f;
#pragma unroll
            for (int k = 0; k < K3C; k++) a = fmaf(uf[k], sW3[e * KPAD + k], a);
            sS3[e * NSLOT_F + s] = a;
        }
    }
    // ---- compute sS2 in-CTA ----
#pragma unroll 1
    for (int t = tid; t < S2U_PER_C; t += 512) {
        const int e = t / NPAIR, pp = t - e * NPAIR;
        const int w = g_pw[pp], v = g_pv[pp];
        float s = 0.f;
#pragma unroll
        for (int k = 0; k < K2C; k++) {
            float u = U2[(w * 16 + v) * K2C + k];
            if (w != v) u += U2[(v * 16 + w) * K2C + k];
            s = fmaf(u, W2[(e * K2C + k) * CDIM + c], s);
        }
        sS2[t] = (ull)__float_as_uint(s);         // (s, 0)
    }
    __syncthreads();

    // ---- per-thread packed x (4 b's) ----
    const int b0 = bg, b1 = bg + 64, b2 = bg + 128, b3 = bg + 192;
    ull xp0[8], xp1[8], xp2[8], xp3[8];
#pragma unroll
    for (int q = 0; q < 8; q++) {
        xp0[q] = pk2(sXs[b0 * 17 + 2 * q], sXs[b0 * 17 + 2 * q + 1]);
        xp1[q] = pk2(sXs[b1 * 17 + 2 * q], sXs[b1 * 17 + 2 * q + 1]);
        xp2[q] = pk2(sXs[b2 * 17 + 2 * q], sXs[b2 * 17 + 2 * q + 1]);
        xp3[q] = pk2(sXs[b3 * 17 + 2 * q], sXs[b3 * 17 + 2 * q + 1]);
    }

    ull acc0 = 0ull, acc1 = 0ull, acc2 = 0ull, acc3 = 0ull;

    // one warp-uniform dispatch; each bucket fully unrolled at compile time
    switch (psplit) {
        case 0: PairChain<0, 0>::run(sS3u2, sS2, sXs, sY4, bg, b0, b1, b2, b3, xp0, xp1, xp2, xp3, acc0, acc1, acc2, acc3); break;
        case 1: PairChain<1, 0>::run(sS3u2, sS2, sXs, sY4, bg, b0, b1, b2, b3, xp0, xp1, xp2, xp3, acc0, acc1, acc2, acc3); break;
        case 2: PairChain<2, 0>::run(sS3u2, sS2, sXs, sY4, bg, b0, b1, b2, b3, xp0, xp1, xp2, xp3, acc0, acc1, acc2, acc3); break;
        case 3: PairChain<3, 0>::run(sS3u2, sS2, sXs, sY4, bg, b0, b1, b2, b3, xp0, xp1, xp2, xp3, acc0, acc1, acc2, acc3); break;
        case 4: PairChain<4, 0>::run(sS3u2, sS2, sXs, sY4, bg, b0, b1, b2, b3, xp0, xp1, xp2, xp3, acc0, acc1, acc2, acc3); break;
        case 5: PairChain<5, 0>::run(sS3u2, sS2, sXs, sY4, bg, b0, b1, b2, b3, xp0, xp1, xp2, xp3, acc0, acc1, acc2, acc3); break;
        case 6: PairChain<6, 0>::run(sS3u2, sS2, sXs, sY4, bg, b0, b1, b2, b3, xp0, xp1, xp2, xp3, acc0, acc1, acc2, acc3); break;
        default: PairChain<7, 0>::run(sS3u2, sS2, sXs, sY4, bg, b0, b1, b2, b3, xp0, xp1, xp2, xp3, acc0, acc1, acc2, acc3); break;
    }

    float lo, hi;
    float s0, s1, s2v, s3v;
    upk2(acc0, lo, hi); s0  = lo + hi;
    upk2(acc1, lo, hi); s1  = lo + hi;
    upk2(acc2, lo, hi); s2v = lo + hi;
    upk2(acc3, lo, hi); s3v = lo + hi;

    // ---- nu=1 (psplit 0 only): sum_e y_e * W1[e,c] * (sum_w U1[w] x_w) ----
    if (psplit == 0) {
        float t0 = 0.f, t1 = 0.f, t2 = 0.f, t3 = 0.f;
#pragma unroll
        for (int w = 0; w < 16; w++) {
            const float uv = U1[w];
            t0 = fmaf(uv, sXs[b0 * 17 + w], t0);
            t1 = fmaf(uv, sXs[b1 * 17 + w], t1);
            t2 = fmaf(uv, sXs[b2 * 17 + w], t2);
            t3 = fmaf(uv, sXs[b3 * 17 + w], t3);
        }
        float add0 = 0.f, add1 = 0.f, add2 = 0.f, add3 = 0.f;
#pragma unroll 1
        for (int e = 0; e < EDIM; e++) {
            const float w1 = W1[e * CDIM + c];
            const float4 yv = sY4[e * 64 + bg];
            add0 = fmaf(yv.x * w1, t0, add0);
            add1 = fmaf(yv.y * w1, t1, add1);
            add2 = fmaf(yv.z * w1, t2, add2);
            add3 = fmaf(yv.w * w1, t3, add3);
        }
        s0 += add0; s1 += add1; s2v += add2; s3v += add3;
    }

    // ---- deterministic cross-split reduction ----
    red[psplit * 256 + b0] = s0;
    red[psplit * 256 + b1] = s1;
    red[psplit * 256 + b2] = s2v;
    red[psplit * 256 + b3] = s3v;
    __syncthreads();
    if (tid < 256) {
        float s = 0.f;
#pragma unroll
        for (int k = 0; k < 8; k++) s += red[k * 256 + tid];
        out[(base + tid) * CDIM + c] = s;
    }
}

// ---- launch --------------------------------------------------------------------
extern "C" void kernel_launch(void* const* d_in, const int* in_sizes, int n_in,
                              void* d_out, int out_size) {
    const float* x  = (const float*)d_in[0];
    const float* y  = (const float*)d_in[1];
    const float* U3 = (const float*)d_in[2];
    const float* U2 = (const float*)d_in[3];
    const float* U1 = (const float*)d_in[4];
    const float* W3 = (const float*)d_in[5];
    const float* W2 = (const float*)d_in[6];
    const float* W1 = (const float*)d_in[7];
    float* out = (float*)d_out;

    cudaFuncSetAttribute(sc_main, cudaFuncAttributeMaxDynamicSharedMemorySize,
                         SMEM_MAIN);

    k_tab<<<1, 256>>>();
    k_sym<<<(NSLOT_F * KPAD + 255) / 256, 256>>>(U3);

    dim3 grid(CDIM, BDIM / 256);
    sc_main<<<grid, 512, SMEM_MAIN>>>(x, y, W3, U2, W2, U1, W1, out);
}